// round 4
// baseline (speedup 1.0000x reference)
#include <cuda_runtime.h>
#include <cuda_fp16.h>
#include <stdint.h>

#define NCTA 128
#define NTHR 256
#define Bsz  256
#define Tn   1024
#define Hn   512
#define APAD 520      // padded smem row (halfs): 260 words % 32 == 4 -> conflict-free
#define GHP  101      // sGhT row stride (floats)

#define OFF_FEAT 1
#define OFF_INP  (1 + Bsz*Hn)
#define OFF_OUT  (1 + Bsz*Hn + Bsz*Tn)

// smem byte offsets
#define SO_W   0
#define SO_A   99840
#define SO_G   133120
#define SO_WO  146048
#define SO_P   148096
#define SO_X   148992
#define SO_SEQ 149120
#define SO_L   149248
#define SMEMSZ 149504

__device__ float    g_h[2][Bsz][Hn];
__device__ float    g_part[8];
__device__ unsigned g_bar_count;
__device__ unsigned g_bar_gen;

__device__ __forceinline__ float sigf(float x){ return __fdividef(1.f, 1.f + __expf(-x)); }
__device__ __forceinline__ float tanhf_(float x){ float e = __expf(2.f*x); return 1.f - __fdividef(2.f, e + 1.f); }

__device__ __forceinline__ void grid_barrier(){
    __syncthreads();
    if (threadIdx.x == 0){
        volatile unsigned* genp = &g_bar_gen;
        unsigned gen = *genp;
        __threadfence();
        if (atomicAdd(&g_bar_count, 1u) == NCTA - 1u){
            g_bar_count = 0u;
            __threadfence();
            *genp = gen + 1u;
        } else {
            while (*genp == gen) { __nanosleep(32); }
        }
        __threadfence();
    }
    __syncthreads();
}

__device__ __forceinline__ void mma16816(float* c, uint32_t a0, uint32_t a1, uint32_t a2, uint32_t a3,
                                         uint32_t b0, uint32_t b1){
    asm volatile("mma.sync.aligned.m16n8k16.row.col.f32.f16.f16.f32 "
                 "{%0,%1,%2,%3},{%4,%5,%6,%7},{%8,%9},{%0,%1,%2,%3};\n"
                 : "+f"(c[0]), "+f"(c[1]), "+f"(c[2]), "+f"(c[3])
                 : "r"(a0), "r"(a1), "r"(a2), "r"(a3), "r"(b0), "r"(b1));
}

// A = h tile (M=32 batch rows), B = W stripe (N=96 gate rows), K=512
__device__ __forceinline__ void mma_step(const half* sW, const half* sA, float* sGhT, int tid){
    int lane = tid & 31, warp = tid >> 5;
    int wm = warp >> 2, wn = warp & 3;          // 2 m-warps x 4 n-warps
    int g = lane >> 2, tg2 = (lane & 3) * 2;
    float acc[3][4];
    #pragma unroll
    for (int nt = 0; nt < 3; nt++)
        #pragma unroll
        for (int i = 0; i < 4; i++) acc[nt][i] = 0.f;
    const half* pA  = sA + (wm*16 + g) * APAD;
    const half* pA2 = pA + 8 * APAD;
    #pragma unroll 8
    for (int kt = 0; kt < 32; kt++){
        int ko = kt * 16 + tg2;
        uint32_t a0 = *(const uint32_t*)(pA  + ko);
        uint32_t a1 = *(const uint32_t*)(pA2 + ko);
        uint32_t a2 = *(const uint32_t*)(pA  + ko + 8);
        uint32_t a3 = *(const uint32_t*)(pA2 + ko + 8);
        #pragma unroll
        for (int nt = 0; nt < 3; nt++){
            const half* pB = sW + (wn*24 + nt*8 + g) * APAD + ko;
            uint32_t b0 = *(const uint32_t*)pB;
            uint32_t b1 = *(const uint32_t*)(pB + 8);
            mma16816(acc[nt], a0, a1, a2, a3, b0, b1);
        }
    }
    int r0 = wm*16 + g;
    #pragma unroll
    for (int nt = 0; nt < 3; nt++){
        int j = wn*24 + nt*8 + tg2;
        sGhT[r0*GHP + j]       = acc[nt][0];
        sGhT[r0*GHP + j + 1]   = acc[nt][1];
        sGhT[(r0+8)*GHP + j]   = acc[nt][2];
        sGhT[(r0+8)*GHP + j+1] = acc[nt][3];
    }
}

__device__ __forceinline__ void load_phase_weights(const float* Wih, const float* Whh,
                                                   const float* bih, const float* bhh,
                                                   half* sW, float* sP, int tid, int U0){
    for (int q = 0; q < 48; q++){
        int li = q*256 + tid;
        int j = li >> 7, c4 = li & 127;
        int grow = (j >> 5) * Hn + U0 + (j & 31);
        float4 v = *(const float4*)&Whh[(size_t)grow * Hn + c4*4];
        *(half2*)&sW[j*APAD + c4*4]     = __floats2half2_rn(v.x, v.y);
        *(half2*)&sW[j*APAD + c4*4 + 2] = __floats2half2_rn(v.z, v.w);
    }
    if (tid < 32){
        int u = tid, gu = U0 + u;
        sP[u]       = Wih[gu];
        sP[32 + u]  = Wih[Hn + gu];
        sP[64 + u]  = Wih[2*Hn + gu];
        sP[96 + u]  = bih[gu] + bhh[gu];
        sP[128 + u] = bih[Hn + gu] + bhh[Hn + gu];
        sP[160 + u] = bih[2*Hn + gu];
        sP[192 + u] = bhh[2*Hn + gu];
    }
}

__device__ __forceinline__ void load_A(int cur, int B0, half* sA, int tid){
    #pragma unroll 4
    for (int q = 0; q < 16; q++){
        int li = q*256 + tid;
        int row = li >> 7, c4 = li & 127;
        float4 v = __ldcv((const float4*)&g_h[cur][B0 + row][c4*4]);
        *(half2*)&sA[row*APAD + c4*4]     = __floats2half2_rn(v.x, v.y);
        *(half2*)&sA[row*APAD + c4*4 + 2] = __floats2half2_rn(v.z, v.w);
    }
}

// returns y (full sum on lanes with (tid&7)==0) for batch row tid>>3
__device__ __forceinline__ float compute_y(const half* sA, const float* sWo, int tid){
    int row = tid >> 3, k0 = (tid & 7) * 64;
    const half2* p = (const half2*)(sA + row*APAD + k0);
    float v = 0.f;
    #pragma unroll 8
    for (int i = 0; i < 32; i++){
        half2 h2 = p[i];
        v += __low2float(h2) * sWo[k0 + 2*i] + __high2float(h2) * sWo[k0 + 2*i + 1];
    }
    v += __shfl_down_sync(0xffffffffu, v, 4);
    v += __shfl_down_sync(0xffffffffu, v, 2);
    v += __shfl_down_sync(0xffffffffu, v, 1);
    return v;
}

__device__ __forceinline__ void epilogue(const float* sGhT, const float* sP, const float* sX,
                                         const int* sSeq, int tid, int B0, int U0,
                                         int cur, int nxt, int t, bool enc){
    #pragma unroll
    for (int q = 0; q < 4; q++){
        int it = q*256 + tid;
        int u = it >> 5, b = it & 31;
        float ghr = sGhT[b*GHP + u];
        float ghz = sGhT[b*GHP + 32 + u];
        float ghn = sGhT[b*GHP + 64 + u];
        float x = sX[b];
        float r = sigf(x * sP[u]      + sP[96 + u]  + ghr);
        float z = sigf(x * sP[32 + u] + sP[128 + u] + ghz);
        float n = tanhf_(x * sP[64 + u] + sP[160 + u] + r * (ghn + sP[192 + u]));
        float hold = g_h[cur][B0 + b][U0 + u];
        float hnew = (1.f - z) * n + z * hold;
        bool valid = enc ? (t < sSeq[b]) : true;
        g_h[nxt][B0 + b][U0 + u] = valid ? hnew : hold;
    }
}

__global__ __launch_bounds__(NTHR, 1)
void gru_ae_kernel(const float* __restrict__ input, const int* __restrict__ seq,
                   const float* __restrict__ eWih, const float* __restrict__ eWhh,
                   const float* __restrict__ ebih, const float* __restrict__ ebhh,
                   const float* __restrict__ dWih, const float* __restrict__ dWhh,
                   const float* __restrict__ dbih, const float* __restrict__ dbhh,
                   const float* __restrict__ Wout, const float* __restrict__ bout,
                   float* __restrict__ out){
    extern __shared__ __align__(16) char sm[];
    half*  sW   = (half*)(sm + SO_W);
    half*  sA   = (half*)(sm + SO_A);
    float* sGhT = (float*)(sm + SO_G);
    float* sWo  = (float*)(sm + SO_WO);
    float* sP   = (float*)(sm + SO_P);
    float* sX   = (float*)(sm + SO_X);
    int*   sSeq = (int*)(sm + SO_SEQ);
    float* sL   = (float*)(sm + SO_L);

    int tid = threadIdx.x;
    int s = blockIdx.x >> 3, bg = blockIdx.x & 7;
    int B0 = bg * 32, U0 = s * 32;
    float bo = bout[0];

    // zero our slice of h[0]; load constants
    #pragma unroll
    for (int q = 0; q < 4; q++){
        int it = q*256 + tid;
        g_h[0][B0 + (it >> 5)][U0 + (it & 31)] = 0.f;
    }
    for (int i = tid; i < Hn; i += NTHR) sWo[i] = Wout[i];
    if (tid < 32) sSeq[tid] = seq[B0 + tid];
    if (tid == 0) sL[0] = 0.f;
    load_phase_weights(eWih, eWhh, ebih, ebhh, sW, sP, tid, U0);
    __syncthreads();
    grid_barrier();   // h[0] fully zeroed chip-wide

    // ---------------- Encoder ----------------
    for (int t = 0; t < Tn; t++){
        int cur = t & 1, nxt = cur ^ 1;
        load_A(cur, B0, sA, tid);
        if (tid < 32) sX[tid] = __ldg(&input[(size_t)(B0 + tid) * Tn + t]);
        __syncthreads();
        mma_step(sW, sA, sGhT, tid);
        __syncthreads();
        epilogue(sGhT, sP, sX, sSeq, tid, B0, U0, cur, nxt, t, true);
        grid_barrier();
    }
    // features: h_final lives at parity 0
    #pragma unroll
    for (int q = 0; q < 4; q++){
        int it = q*256 + tid;
        int b = it >> 5, u = it & 31;
        out[OFF_FEAT + (size_t)(B0 + b) * Hn + U0 + u] = g_h[0][B0 + b][U0 + u];
    }
    load_phase_weights(dWih, dWhh, dbih, dbhh, sW, sP, tid, U0);
    __syncthreads();

    // ---------------- Decoder ----------------
    float loss_acc = 0.f;
    for (int t = 0; t < Tn; t++){
        int cur = t & 1, nxt = cur ^ 1;
        load_A(cur, B0, sA, tid);
        __syncthreads();
        float y = compute_y(sA, sWo, tid);
        if ((tid & 7) == 0){
            int b = tid >> 3;
            float yv = y + bo;
            sX[b] = (t == 0) ? 0.f : yv;
            if (t > 0 && s == 0){
                out[OFF_OUT + (size_t)(B0 + b) * Tn + (t - 1)] = yv;
                if ((t - 1) < sSeq[b]){
                    float d = __ldg(&input[(size_t)(B0 + b) * Tn + (t - 1)]) - yv;
                    loss_acc += d * d;
                }
            }
        }
        __syncthreads();
        mma_step(sW, sA, sGhT, tid);
        __syncthreads();
        epilogue(sGhT, sP, sX, sSeq, tid, B0, U0, cur, nxt, t, false);
        grid_barrier();
    }
    // final y_1023 (h_1024 at parity 0)
    load_A(0, B0, sA, tid);
    __syncthreads();
    {
        float y = compute_y(sA, sWo, tid);
        if ((tid & 7) == 0 && s == 0){
            int b = tid >> 3;
            float yv = y + bo;
            out[OFF_OUT + (size_t)(B0 + b) * Tn + (Tn - 1)] = yv;
            if ((Tn - 1) < sSeq[b]){
                float d = __ldg(&input[(size_t)(B0 + b) * Tn + (Tn - 1)]) - yv;
                loss_acc += d * d;
            }
        }
    }
    __syncthreads();
    if (s == 0){
        if ((tid & 7) == 0) atomicAdd(sL, loss_acc);
        __syncthreads();
        if (tid == 0) g_part[bg] = sL[0];
    }
    grid_barrier();
    if (blockIdx.x == 0 && tid == 0){
        float tot = 0.f;
        #pragma unroll
        for (int i = 0; i < 8; i++) tot += g_part[i];
        long cnt = 0;
        for (int b = 0; b < Bsz; b++) cnt += seq[b];
        out[0] = tot / (float)cnt;
    }
}

extern "C" void kernel_launch(void* const* d_in, const int* in_sizes, int n_in,
                              void* d_out, int out_size){
    (void)in_sizes; (void)n_in; (void)out_size;
    const float* input = (const float*)d_in[0];
    const int*   seq   = (const int*)d_in[1];
    const float* eWih  = (const float*)d_in[2];
    const float* eWhh  = (const float*)d_in[3];
    const float* ebih  = (const float*)d_in[4];
    const float* ebhh  = (const float*)d_in[5];
    const float* dWih  = (const float*)d_in[6];
    const float* dWhh  = (const float*)d_in[7];
    const float* dbih  = (const float*)d_in[8];
    const float* dbhh  = (const float*)d_in[9];
    const float* Wout  = (const float*)d_in[10];
    const float* bo    = (const float*)d_in[11];
    float* out = (float*)d_out;

    cudaFuncSetAttribute(gru_ae_kernel, cudaFuncAttributeMaxDynamicSharedMemorySize, SMEMSZ);

    // echo input block of the output tuple
    cudaMemcpyAsync(out + OFF_INP, input, (size_t)Bsz * Tn * sizeof(float),
                    cudaMemcpyDeviceToDevice, 0);
    gru_ae_kernel<<<NCTA, NTHR, SMEMSZ, 0>>>(input, seq, eWih, eWhh, ebih, ebhh,
                                             dWih, dWhh, dbih, dbhh, Wout, bo, out);
}

// round 5
// speedup vs baseline: 1.4075x; 1.4075x over previous
#include <cuda_runtime.h>
#include <cuda_fp16.h>
#include <stdint.h>

#define NCTA 128
#define NTHR 256
#define Bsz  256
#define Tn   1024
#define Hn   512
#define APAD 520      // padded smem row (halfs): 260 words % 32 == 4 -> conflict-free
#define GHP  101      // sGhT row stride (floats)
#define XBS  36       // sXB row stride (floats), 144B: 16B-aligned rows, %32==4

#define OFF_FEAT 1
#define OFF_INP  (1 + Bsz*Hn)
#define OFF_OUT  (1 + Bsz*Hn + Bsz*Tn)

// smem byte offsets
#define SO_W   0         // half sW[96][APAD]   = 99840
#define SO_A   99840     // half sA[32][APAD]   = 33280
#define SO_G   133120    // float sGhT[32][GHP] = 12928
#define SO_WO  146048    // float sWo[512]      = 2048
#define SO_P   148096    // float sP[256]       = 1024
#define SO_XB  149120    // float sXB[32][XBS]  = 4608
#define SO_X   153728    // float sX[32]        = 128
#define SO_SEQ 153856    // int   sSeq[32]      = 128
#define SO_L   153984    // float sL[1], int sCnt[1]
#define SMEMSZ 154048

__device__ __half   g_hh[2][Bsz][Hn];   // fp16 hidden state (MMA feed)
__device__ float    g_loss;
__device__ unsigned g_done;
__device__ unsigned g_cnt0, g_gen0;          // one-shot global barrier
__device__ unsigned g_cnt8[8][64];           // per-batch-group barriers (256B apart)
__device__ unsigned g_gen8[8][64];

__device__ __forceinline__ float sigf(float x){ return __fdividef(1.f, 1.f + __expf(-x)); }
__device__ __forceinline__ float tanhf_(float x){ float e = __expf(2.f*x); return 1.f - __fdividef(2.f, e + 1.f); }

__device__ __forceinline__ uint32_t smaddr(const void* p){
    return (uint32_t)__cvta_generic_to_shared(p);
}

__device__ __forceinline__ void bar_sync(unsigned* cnt, unsigned* gen, unsigned n){
    __syncthreads();
    if (threadIdx.x == 0){
        volatile unsigned* gp = gen;
        unsigned v = *gp;
        __threadfence();
        if (atomicAdd(cnt, 1u) == n - 1u){
            *cnt = 0u;
            __threadfence();
            *gp = v + 1u;
        } else {
            while (*gp == v) { __nanosleep(64); }
        }
        __threadfence();
    }
    __syncthreads();
}

__device__ __forceinline__ void mma16816(float* c, uint32_t a0, uint32_t a1, uint32_t a2, uint32_t a3,
                                         uint32_t b0, uint32_t b1){
    asm volatile("mma.sync.aligned.m16n8k16.row.col.f32.f16.f16.f32 "
                 "{%0,%1,%2,%3},{%4,%5,%6,%7},{%8,%9},{%0,%1,%2,%3};\n"
                 : "+f"(c[0]), "+f"(c[1]), "+f"(c[2]), "+f"(c[3])
                 : "r"(a0), "r"(a1), "r"(a2), "r"(a3), "r"(b0), "r"(b1));
}

// gh^T tile: A = h (M=32 batch), B = W stripe (N=96 gate rows), K=512, via ldmatrix
__device__ __forceinline__ void mma_step(const half* sW, const half* sA, float* sGhT, int tid){
    int lane = tid & 31, warp = tid >> 5;
    int wm = warp >> 2, wn = warp & 3;          // 2 m-warps x 4 n-warps (m16 x n24 each)
    int grp = lane >> 3, l7 = lane & 7, l15 = lane & 15;

    // A m16k16 ldmatrix.x4: m0 rows0-7/k0, m1 rows8-15/k0, m2 rows0-7/k8, m3 rows8-15/k8
    int rowA = wm*16 + (grp & 1)*8 + l7;
    uint32_t aA = smaddr(sA + rowA*APAD + (grp >> 1)*8);
    // B (nt0,nt1) ldmatrix.x4: m0 nt0/k0, m1 nt0/k8, m2 nt1/k0, m3 nt1/k8
    int rowB = wn*24 + (grp >> 1)*8 + l7;
    uint32_t aB = smaddr(sW + rowB*APAD + (grp & 1)*8);
    // B nt2 ldmatrix.x2: m0 k0, m1 k8 (lanes 0-15 supply addresses)
    int rowC = wn*24 + 16 + (l15 & 7);
    uint32_t aC = smaddr(sW + rowC*APAD + (l15 >> 3)*8);

    float acc[3][4];
    #pragma unroll
    for (int nt = 0; nt < 3; nt++)
        #pragma unroll
        for (int i = 0; i < 4; i++) acc[nt][i] = 0.f;

    #pragma unroll 4
    for (int kt = 0; kt < 32; kt++){
        uint32_t a0,a1,a2,a3, b0,b1,b2,b3, c0,c1;
        asm volatile("ldmatrix.sync.aligned.m8n8.x4.shared.b16 {%0,%1,%2,%3},[%4];"
                     : "=r"(a0),"=r"(a1),"=r"(a2),"=r"(a3) : "r"(aA));
        asm volatile("ldmatrix.sync.aligned.m8n8.x4.shared.b16 {%0,%1,%2,%3},[%4];"
                     : "=r"(b0),"=r"(b1),"=r"(b2),"=r"(b3) : "r"(aB));
        asm volatile("ldmatrix.sync.aligned.m8n8.x2.shared.b16 {%0,%1},[%2];"
                     : "=r"(c0),"=r"(c1) : "r"(aC));
        mma16816(acc[0], a0,a1,a2,a3, b0,b1);
        mma16816(acc[1], a0,a1,a2,a3, b2,b3);
        mma16816(acc[2], a0,a1,a2,a3, c0,c1);
        aA += 32; aB += 32; aC += 32;   // 16 halfs per k-tile
    }
    int g = lane >> 2, tg2 = (lane & 3)*2;
    int r0 = wm*16 + g;
    #pragma unroll
    for (int nt = 0; nt < 3; nt++){
        int j = wn*24 + nt*8 + tg2;
        sGhT[r0*GHP + j]       = acc[nt][0];
        sGhT[r0*GHP + j + 1]   = acc[nt][1];
        sGhT[(r0+8)*GHP + j]   = acc[nt][2];
        sGhT[(r0+8)*GHP + j+1] = acc[nt][3];
    }
}

__device__ __forceinline__ void load_phase_weights(const float* Wih, const float* Whh,
                                                   const float* bih, const float* bhh,
                                                   half* sW, float* sP, int tid, int U0){
    for (int q = 0; q < 48; q++){
        int li = q*256 + tid;
        int j = li >> 7, c4 = li & 127;
        int grow = (j >> 5) * Hn + U0 + (j & 31);
        float4 v = *(const float4*)&Whh[(size_t)grow * Hn + c4*4];
        *(half2*)&sW[j*APAD + c4*4]     = __floats2half2_rn(v.x, v.y);
        *(half2*)&sW[j*APAD + c4*4 + 2] = __floats2half2_rn(v.z, v.w);
    }
    if (tid < 32){
        int u = tid, gu = U0 + u;
        sP[u]       = Wih[gu];
        sP[32 + u]  = Wih[Hn + gu];
        sP[64 + u]  = Wih[2*Hn + gu];
        sP[96 + u]  = bih[gu] + bhh[gu];
        sP[128 + u] = bih[Hn + gu] + bhh[Hn + gu];
        sP[160 + u] = bih[2*Hn + gu];
        sP[192 + u] = bhh[2*Hn + gu];
    }
}

// copy 32x512 halfs from g_hh[cur][B0..] into sA (direct, no conversion)
__device__ __forceinline__ void load_A(int cur, int B0, half* sA, int tid){
    const uint4* src = (const uint4*)&g_hh[cur][B0][0];   // row stride = 64 uint4
    #pragma unroll
    for (int q = 0; q < 8; q++){
        int li = q*256 + tid;
        int row = li >> 6, c = li & 63;
        uint4 v = __ldcg(src + row*64 + c);
        *(uint4*)&sA[row*APAD + c*8] = v;
    }
}

// y for batch row tid>>3, full sum on lanes with (tid&7)==0
__device__ __forceinline__ float compute_y(const half* sA, const float* sWo, int tid){
    int row = tid >> 3, k0 = (tid & 7) * 64;
    const half2* p = (const half2*)(sA + row*APAD + k0);
    float v = 0.f;
    #pragma unroll 8
    for (int i = 0; i < 32; i++){
        half2 h2 = p[i];
        v += __low2float(h2) * sWo[k0 + 2*i] + __high2float(h2) * sWo[k0 + 2*i + 1];
    }
    v += __shfl_down_sync(0xffffffffu, v, 4);
    v += __shfl_down_sync(0xffffffffu, v, 2);
    v += __shfl_down_sync(0xffffffffu, v, 1);
    return v;
}

// thread owns (b = q*8 + tid>>5, u = tid&31); fp32 master in hreg
__device__ __forceinline__ void epilogue(const float* sGhT, const float* sP,
                                         const float* xbase, int xstride, int xcol,
                                         const int* sSeq, float* hreg,
                                         int tid, int B0, int U0, int nxt, int t, bool enc){
    int u = tid & 31;
    float wir = sP[u],      wiz = sP[32+u],  win = sP[64+u];
    float br  = sP[96+u],   bz  = sP[128+u];
    float bin = sP[160+u],  bhn = sP[192+u];
    #pragma unroll
    for (int q = 0; q < 4; q++){
        int b = q*8 + (tid >> 5);
        float x   = xbase[b*xstride + xcol];
        float ghr = sGhT[b*GHP + u];
        float ghz = sGhT[b*GHP + 32 + u];
        float ghn = sGhT[b*GHP + 64 + u];
        float r = sigf(x*wir + br + ghr);
        float z = sigf(x*wiz + bz + ghz);
        float n = tanhf_(x*win + bin + r*(ghn + bhn));
        float hnew = (1.f - z)*n + z*hreg[q];
        bool valid = enc ? (t < sSeq[b]) : true;
        if (valid) hreg[q] = hnew;
        g_hh[nxt][B0 + b][U0 + u] = __float2half(hreg[q]);   // coalesced 64B per warp
    }
}

__global__ __launch_bounds__(NTHR, 1)
void gru_ae_kernel(const float* __restrict__ input, const int* __restrict__ seq,
                   const float* __restrict__ eWih, const float* __restrict__ eWhh,
                   const float* __restrict__ ebih, const float* __restrict__ ebhh,
                   const float* __restrict__ dWih, const float* __restrict__ dWhh,
                   const float* __restrict__ dbih, const float* __restrict__ dbhh,
                   const float* __restrict__ Wout, const float* __restrict__ bout,
                   float* __restrict__ out){
    extern __shared__ __align__(16) char sm[];
    half*  sW   = (half*)(sm + SO_W);
    half*  sA   = (half*)(sm + SO_A);
    float* sGhT = (float*)(sm + SO_G);
    float* sWo  = (float*)(sm + SO_WO);
    float* sP   = (float*)(sm + SO_P);
    float* sXB  = (float*)(sm + SO_XB);
    float* sX   = (float*)(sm + SO_X);
    int*   sSeq = (int*)(sm + SO_SEQ);
    float* sL   = (float*)(sm + SO_L);
    int*   sCnt = (int*)(sm + SO_L + 8);

    int tid = threadIdx.x;
    int s = blockIdx.x >> 3, bg = blockIdx.x & 7;
    int B0 = bg * 32, U0 = s * 32;
    unsigned* cnt = &g_cnt8[bg][0];
    unsigned* gen = &g_gen8[bg][0];
    float bo = bout[0];
    float hreg[4] = {0.f, 0.f, 0.f, 0.f};

    if (blockIdx.x == 0 && tid == 0){ g_loss = 0.f; g_done = 0u; }

    // zero own slice of g_hh[0]
    {
        int u = tid & 31;
        #pragma unroll
        for (int q = 0; q < 4; q++)
            g_hh[0][B0 + q*8 + (tid >> 5)][U0 + u] = __float2half(0.f);
    }
    for (int i = tid; i < Hn; i += NTHR) sWo[i] = Wout[i];
    if (tid < 32) sSeq[tid] = seq[B0 + tid];
    if (tid == 0){ sL[0] = 0.f; sCnt[0] = 0; }
    __syncthreads();
    // total valid count (all CTAs compute; only CTA0 uses)
    {
        int v = seq[tid];
        #pragma unroll
        for (int o = 16; o > 0; o >>= 1) v += __shfl_down_sync(0xffffffffu, v, o);
        if ((tid & 31) == 0) atomicAdd(sCnt, v);
    }
    load_phase_weights(eWih, eWhh, ebih, ebhh, sW, sP, tid, U0);
    __syncthreads();
    bar_sync(&g_cnt0, &g_gen0, NCTA);   // once: h[0] zeros + g_done reset visible chip-wide

    // ---------------- Encoder ----------------
    for (int t = 0; t < Tn; t++){
        int cur = t & 1, nxt = cur ^ 1;
        load_A(cur, B0, sA, tid);
        if ((t & 31) == 0){   // refill 32-step input block
            int row = tid >> 3, c4 = (tid & 7) * 4;
            float4 v = *(const float4*)&input[(size_t)(B0 + row) * Tn + t + c4];
            *(float4*)&sXB[row*XBS + c4] = v;
        }
        __syncthreads();
        mma_step(sW, sA, sGhT, tid);
        __syncthreads();
        epilogue(sGhT, sP, sXB, XBS, t & 31, sSeq, hreg, tid, B0, U0, nxt, t, true);
        bar_sync(cnt, gen, 16);
    }
    // features = h_final (registers)
    {
        int u = tid & 31;
        #pragma unroll
        for (int q = 0; q < 4; q++){
            int b = q*8 + (tid >> 5);
            out[OFF_FEAT + (size_t)(B0 + b) * Hn + U0 + u] = hreg[q];
        }
    }
    load_phase_weights(dWih, dWhh, dbih, dbhh, sW, sP, tid, U0);
    __syncthreads();

    // ---------------- Decoder ----------------
    float loss_acc = 0.f;
    for (int t = 0; t < Tn; t++){
        int cur = t & 1, nxt = cur ^ 1;
        load_A(cur, B0, sA, tid);
        __syncthreads();
        float y = compute_y(sA, sWo, tid);
        if ((tid & 7) == 0){
            int b = tid >> 3;
            float yv = y + bo;
            sX[b] = (t == 0) ? 0.f : yv;
            if (t > 0 && s == 0){
                out[OFF_OUT + (size_t)(B0 + b) * Tn + (t - 1)] = yv;
                if ((t - 1) < sSeq[b]){
                    float d = __ldg(&input[(size_t)(B0 + b) * Tn + (t - 1)]) - yv;
                    loss_acc += d * d;
                }
            }
        }
        __syncthreads();
        mma_step(sW, sA, sGhT, tid);
        __syncthreads();
        epilogue(sGhT, sP, sX, 1, 0, sSeq, hreg, tid, B0, U0, nxt, t, false);
        bar_sync(cnt, gen, 16);
    }
    // final y_1023 from h_1024 (parity 0)
    load_A(0, B0, sA, tid);
    __syncthreads();
    {
        float y = compute_y(sA, sWo, tid);
        if ((tid & 7) == 0 && s == 0){
            int b = tid >> 3;
            float yv = y + bo;
            out[OFF_OUT + (size_t)(B0 + b) * Tn + (Tn - 1)] = yv;
            if ((Tn - 1) < sSeq[b]){
                float d = __ldg(&input[(size_t)(B0 + b) * Tn + (Tn - 1)]) - yv;
                loss_acc += d * d;
            }
        }
    }
    __syncthreads();
    if (s == 0){
        if ((tid & 7) == 0) atomicAdd(sL, loss_acc);
        __syncthreads();
        if (tid == 0){
            atomicAdd(&g_loss, sL[0]);
            __threadfence();
            atomicAdd(&g_done, 1u);
        }
    }
    if (blockIdx.x == 0 && tid == 0){
        while (atomicAdd(&g_done, 0u) < 8u) { __nanosleep(128); }
        __threadfence();
        float tot = atomicAdd(&g_loss, 0.f);
        out[0] = tot / (float)sCnt[0];
    }
}

extern "C" void kernel_launch(void* const* d_in, const int* in_sizes, int n_in,
                              void* d_out, int out_size){
    (void)in_sizes; (void)n_in; (void)out_size;
    const float* input = (const float*)d_in[0];
    const int*   seq   = (const int*)d_in[1];
    const float* eWih  = (const float*)d_in[2];
    const float* eWhh  = (const float*)d_in[3];
    const float* ebih  = (const float*)d_in[4];
    const float* ebhh  = (const float*)d_in[5];
    const float* dWih  = (const float*)d_in[6];
    const float* dWhh  = (const float*)d_in[7];
    const float* dbih  = (const float*)d_in[8];
    const float* dbhh  = (const float*)d_in[9];
    const float* Wout  = (const float*)d_in[10];
    const float* bo    = (const float*)d_in[11];
    float* out = (float*)d_out;

    cudaFuncSetAttribute(gru_ae_kernel, cudaFuncAttributeMaxDynamicSharedMemorySize, SMEMSZ);

    cudaMemcpyAsync(out + OFF_INP, input, (size_t)Bsz * Tn * sizeof(float),
                    cudaMemcpyDeviceToDevice, 0);
    gru_ae_kernel<<<NCTA, NTHR, SMEMSZ, 0>>>(input, seq, eWih, eWhh, ebih, ebhh,
                                             dWih, dWhh, dbih, dbhh, Wout, bo, out);
}

// round 6
// speedup vs baseline: 2.0720x; 1.4722x over previous
#include <cuda_runtime.h>
#include <cuda_fp16.h>
#include <stdint.h>

#define NCTA 128
#define NTHR 256
#define Bsz  256
#define Tn   1024
#define Hn   512
#define APAD 520      // padded smem row (halfs): 260 words % 32 == 4 -> conflict-free
#define XBS  36       // sXB row stride (floats)

#define OFF_FEAT 1
#define OFF_INP  (1 + Bsz*Hn)
#define OFF_OUT  (1 + Bsz*Hn + Bsz*Tn)

// smem byte offsets
#define SO_W   0         // half sW[104][APAD] = 108160  (96 gate rows + Wout row + 7 zero)
#define SO_A   108160    // half sA[32][APAD]  = 33280
#define SO_P   141440    // float sP[7][32]    = 896 (pad 1024)
#define SO_XB  142464    // float sXB[32][XBS] = 4608
#define SO_X   147072    // float sX[32]
#define SO_SEQ 147200    // int sSeq[32]
#define SO_L   147328    // float sL; int sCnt
#define SO_BAR 147344    // unsigned sBar[2]
#define SMEMSZ 147456

__device__ __half   g_hh[2][Bsz][Hn];   // fp16 hidden state (MMA feed)
__device__ float    g_loss;
__device__ unsigned g_done;
__device__ unsigned g_cnt0, g_gen0;     // one-shot global barrier (monotonic)
__device__ unsigned g_cnt8[8][64];      // per-batch-group barriers (256B apart)
__device__ unsigned g_gen8[8][64];

__device__ __forceinline__ float sigf(float x){ return __fdividef(1.f, 1.f + __expf(-x)); }
__device__ __forceinline__ float tanhf_(float x){ float e = __expf(2.f*x); return 1.f - __fdividef(2.f, e + 1.f); }
__device__ __forceinline__ uint32_t smaddr(const void* p){ return (uint32_t)__cvta_generic_to_shared(p); }

__device__ __forceinline__ unsigned ld_acq(unsigned* p){
    unsigned v;
    asm volatile("ld.acquire.gpu.global.u32 %0,[%1];" : "=r"(v) : "l"(p) : "memory");
    return v;
}
__device__ __forceinline__ void st_rel(unsigned* p, unsigned v){
    asm volatile("st.release.gpu.global.u32 [%0],%1;" :: "l"(p), "r"(v) : "memory");
}
__device__ __forceinline__ unsigned atom_rel_add(unsigned* p, unsigned v){
    unsigned old;
    asm volatile("atom.release.gpu.global.add.u32 %0,[%1],%2;" : "=r"(old) : "l"(p), "r"(v) : "memory");
    return old;
}

// Monotonic barrier: ph = absolute generation target, n participants.
__device__ __forceinline__ void barN(unsigned* cnt, unsigned* gen, unsigned ph, unsigned n){
    __syncthreads();
    if (threadIdx.x == 0){
        unsigned old = atom_rel_add(cnt, 1u);
        if (old == ph * n - 1u){
            st_rel(gen, ph);
        } else {
            while ((int)(ld_acq(gen) - ph) < 0) __nanosleep(32);
        }
    }
    __syncthreads();
}

__device__ __forceinline__ void mma16816(float* c, uint32_t a0, uint32_t a1, uint32_t a2, uint32_t a3,
                                         uint32_t b0, uint32_t b1){
    asm volatile("mma.sync.aligned.m16n8k16.row.col.f32.f16.f16.f32 "
                 "{%0,%1,%2,%3},{%4,%5,%6,%7},{%8,%9},{%0,%1,%2,%3};\n"
                 : "+f"(c[0]), "+f"(c[1]), "+f"(c[2]), "+f"(c[3])
                 : "r"(a0), "r"(a1), "r"(a2), "r"(a3), "r"(b0), "r"(b1));
}

// A = h (M=32 batch), B = gate-interleaved W (N=96) [+ y tile rows 96..103], K=512.
// Warp wn owns units [wn*8, wn*8+8); its 3 n8 tiles are gates r,z,n for those units.
template<bool WY>
__device__ __forceinline__ void mma_step(const half* sW, const half* sA, int tid,
                                         float (&acc)[3][4], float (&accY)[4]){
    int lane = tid & 31, warp = tid >> 5;
    int wm = warp >> 2, wn = warp & 3;
    int grp = lane >> 3, l7 = lane & 7, l15 = lane & 15;

    int rowA = wm*16 + (grp & 1)*8 + l7;
    uint32_t aA = smaddr(sA + rowA*APAD + (grp >> 1)*8);
    int rowB = wn*24 + (grp >> 1)*8 + l7;
    uint32_t aB = smaddr(sW + rowB*APAD + (grp & 1)*8);
    int rowC = wn*24 + 16 + (l15 & 7);
    uint32_t aC = smaddr(sW + rowC*APAD + (l15 >> 3)*8);
    uint32_t aY = smaddr(sW + (96 + (l15 & 7))*APAD + (l15 >> 3)*8);
    const bool doY = WY && (wn == 0);

    #pragma unroll
    for (int nt = 0; nt < 3; nt++)
        #pragma unroll
        for (int i = 0; i < 4; i++) acc[nt][i] = 0.f;
    #pragma unroll
    for (int i = 0; i < 4; i++) accY[i] = 0.f;

    #pragma unroll 4
    for (int kt = 0; kt < 32; kt++){
        uint32_t a0,a1,a2,a3, b0,b1,b2,b3, c0,c1;
        asm volatile("ldmatrix.sync.aligned.m8n8.x4.shared.b16 {%0,%1,%2,%3},[%4];"
                     : "=r"(a0),"=r"(a1),"=r"(a2),"=r"(a3) : "r"(aA));
        asm volatile("ldmatrix.sync.aligned.m8n8.x4.shared.b16 {%0,%1,%2,%3},[%4];"
                     : "=r"(b0),"=r"(b1),"=r"(b2),"=r"(b3) : "r"(aB));
        asm volatile("ldmatrix.sync.aligned.m8n8.x2.shared.b16 {%0,%1},[%2];"
                     : "=r"(c0),"=r"(c1) : "r"(aC));
        mma16816(acc[0], a0,a1,a2,a3, b0,b1);
        mma16816(acc[1], a0,a1,a2,a3, b2,b3);
        mma16816(acc[2], a0,a1,a2,a3, c0,c1);
        if (doY){
            uint32_t y0,y1;
            asm volatile("ldmatrix.sync.aligned.m8n8.x2.shared.b16 {%0,%1},[%2];"
                         : "=r"(y0),"=r"(y1) : "r"(aY));
            mma16816(accY, a0,a1,a2,a3, y0,y1);
            aY += 32;
        }
        aA += 32; aB += 32; aC += 32;
    }
}

// gate-interleaved rows: j = wn*24 + gate*8 + uu  <->  Whh row gate*Hn + U0 + wn*8 + uu
// rows 96..103: Wout row + zeros.
__device__ __forceinline__ void load_phase_weights(const float* Wih, const float* Whh,
                                                   const float* bih, const float* bhh,
                                                   const float* Wout,
                                                   half* sW, float* sP, int tid, int U0){
    for (int q = 0; q < 48; q++){
        int li = q*256 + tid;
        int j = li >> 7, c4 = li & 127;
        int wn = j / 24, rem = j % 24;
        int grow = (rem >> 3) * Hn + U0 + wn*8 + (rem & 7);
        float4 v = *(const float4*)&Whh[(size_t)grow * Hn + c4*4];
        *(half2*)&sW[j*APAD + c4*4]     = __floats2half2_rn(v.x, v.y);
        *(half2*)&sW[j*APAD + c4*4 + 2] = __floats2half2_rn(v.z, v.w);
    }
    // rows 96..103
    for (int q = 0; q < 4; q++){
        int li = q*256 + tid;
        int j = 96 + (li >> 7), c4 = li & 127;
        half2 z = __floats2half2_rn(0.f, 0.f);
        half2 h0 = z, h1 = z;
        if (j == 96){
            float4 v = *(const float4*)&Wout[c4*4];
            h0 = __floats2half2_rn(v.x, v.y);
            h1 = __floats2half2_rn(v.z, v.w);
        }
        *(half2*)&sW[j*APAD + c4*4]     = h0;
        *(half2*)&sW[j*APAD + c4*4 + 2] = h1;
    }
    if (tid < 32){
        int u = tid, gu = U0 + u;
        sP[u]       = Wih[gu];
        sP[32 + u]  = Wih[Hn + gu];
        sP[64 + u]  = Wih[2*Hn + gu];
        sP[96 + u]  = bih[gu] + bhh[gu];
        sP[128 + u] = bih[Hn + gu] + bhh[Hn + gu];
        sP[160 + u] = bih[2*Hn + gu];
        sP[192 + u] = bhh[2*Hn + gu];
    }
}

__device__ __forceinline__ void load_A(int cur, int B0, half* sA, int tid){
    const uint4* src = (const uint4*)&g_hh[cur][B0][0];   // row stride = 64 uint4
    #pragma unroll
    for (int q = 0; q < 8; q++){
        int li = q*256 + tid;
        int row = li >> 6, c = li & 63;
        uint4 v = __ldcg(src + row*64 + c);
        *(uint4*)&sA[row*APAD + c*8] = v;
    }
}

// Epilogue straight from mma fragments; thread owns 4 (b,u) pairs (stable across steps).
__device__ __forceinline__ void epilogue_frag(const float (&acc)[3][4], const float* sP,
        const float* xb, int xstride, const int* sSeq, float* hreg,
        int tid, int B0, int U0, int nxt, int t, bool enc){
    int lane = tid & 31, warp = tid >> 5;
    int wm = warp >> 2, wn = warp & 3;
    int g = lane >> 2, tg2 = (lane & 3)*2;
    int u0 = wn*8 + tg2;
    float2 wir = *(const float2*)&sP[u0];
    float2 wiz = *(const float2*)&sP[32+u0];
    float2 win = *(const float2*)&sP[64+u0];
    float2 br  = *(const float2*)&sP[96+u0];
    float2 bz  = *(const float2*)&sP[128+u0];
    float2 bin = *(const float2*)&sP[160+u0];
    float2 bhn = *(const float2*)&sP[192+u0];
    #pragma unroll
    for (int j = 0; j < 2; j++){
        int b = wm*16 + g + j*8;
        float x = xb[b*xstride];
        bool valid = enc ? (t < sSeq[b]) : true;
        float r0 = sigf(x*wir.x + br.x + acc[0][j*2]);
        float z0 = sigf(x*wiz.x + bz.x + acc[1][j*2]);
        float n0 = tanhf_(x*win.x + bin.x + r0*(acc[2][j*2] + bhn.x));
        float h0 = (1.f - z0)*n0 + z0*hreg[j*2];
        if (valid) hreg[j*2] = h0;
        float r1 = sigf(x*wir.y + br.y + acc[0][j*2+1]);
        float z1 = sigf(x*wiz.y + bz.y + acc[1][j*2+1]);
        float n1 = tanhf_(x*win.y + bin.y + r1*(acc[2][j*2+1] + bhn.y));
        float h1 = (1.f - z1)*n1 + z1*hreg[j*2+1];
        if (valid) hreg[j*2+1] = h1;
        *(__half2*)&g_hh[nxt][B0 + b][U0 + u0] = __floats2half2_rn(hreg[j*2], hreg[j*2+1]);
    }
}

__global__ __launch_bounds__(NTHR, 1)
void gru_ae_kernel(const float* __restrict__ input, const int* __restrict__ seq,
                   const float* __restrict__ eWih, const float* __restrict__ eWhh,
                   const float* __restrict__ ebih, const float* __restrict__ ebhh,
                   const float* __restrict__ dWih, const float* __restrict__ dWhh,
                   const float* __restrict__ dbih, const float* __restrict__ dbhh,
                   const float* __restrict__ Wout, const float* __restrict__ bout,
                   float* __restrict__ out){
    extern __shared__ __align__(16) char sm[];
    half*  sW   = (half*)(sm + SO_W);
    half*  sA   = (half*)(sm + SO_A);
    float* sP   = (float*)(sm + SO_P);
    float* sXB  = (float*)(sm + SO_XB);
    float* sX   = (float*)(sm + SO_X);
    int*   sSeq = (int*)(sm + SO_SEQ);
    float* sL   = (float*)(sm + SO_L);
    int*   sCnt = (int*)(sm + SO_L + 4);
    unsigned* sBar = (unsigned*)(sm + SO_BAR);

    int tid = threadIdx.x;
    int lane = tid & 31, warp = tid >> 5;
    int wm = warp >> 2, wn = warp & 3;
    int s = blockIdx.x >> 3, bg = blockIdx.x & 7;
    int B0 = bg * 32, U0 = s * 32;
    unsigned* cnt = &g_cnt8[bg][0];
    unsigned* gen = &g_gen8[bg][0];
    float bo = bout[0];
    float hreg[4] = {0.f, 0.f, 0.f, 0.f};
    float acc[3][4], accY[4];

    if (blockIdx.x == 0 && tid == 0){ g_loss = 0.f; g_done = 0u; }
    if (tid == 0){ sBar[0] = g_gen0; sBar[1] = *gen; }   // persistent base (pre-arrival safe)

    // zero own slice of g_hh[0] (fragment-keyed ownership)
    {
        int g = lane >> 2, tg2 = (lane & 3)*2;
        int u0 = U0 + wn*8 + tg2;
        __half2 z2 = __floats2half2_rn(0.f, 0.f);
        *(__half2*)&g_hh[0][B0 + wm*16 + g][u0]     = z2;
        *(__half2*)&g_hh[0][B0 + wm*16 + g + 8][u0] = z2;
    }
    if (tid < 32) sSeq[tid] = seq[B0 + tid];
    if (tid == 0){ sL[0] = 0.f; sCnt[0] = 0; }
    __syncthreads();
    unsigned S0 = sBar[0], S = sBar[1];
    {
        int v = seq[tid];
        #pragma unroll
        for (int o = 16; o > 0; o >>= 1) v += __shfl_down_sync(0xffffffffu, v, o);
        if ((tid & 31) == 0) atomicAdd(sCnt, v);
    }
    load_phase_weights(eWih, eWhh, ebih, ebhh, Wout, sW, sP, tid, U0);
    barN(&g_cnt0, &g_gen0, S0 + 1u, NCTA);   // h[0] zeros + loss reset visible chip-wide

    unsigned ph = S;

    // ---------------- Encoder ----------------
    for (int t = 0; t < Tn; t++){
        int cur = t & 1, nxt = cur ^ 1;
        load_A(cur, B0, sA, tid);
        if ((t & 31) == 0){
            int row = tid >> 3, c4 = (tid & 7) * 4;
            float4 v = *(const float4*)&input[(size_t)(B0 + row) * Tn + t + c4];
            *(float4*)&sXB[row*XBS + c4] = v;
        }
        __syncthreads();
        mma_step<false>(sW, sA, tid, acc, accY);
        epilogue_frag(acc, sP, sXB + (t & 31), XBS, sSeq, hreg, tid, B0, U0, nxt, t, true);
        barN(cnt, gen, ++ph, 16u);
    }
    // features = h_final (registers, fragment-keyed)
    {
        int g = lane >> 2, tg2 = (lane & 3)*2;
        int u0 = U0 + wn*8 + tg2;
        #pragma unroll
        for (int j = 0; j < 2; j++){
            int b = B0 + wm*16 + g + j*8;
            out[OFF_FEAT + (size_t)b * Hn + u0]     = hreg[j*2];
            out[OFF_FEAT + (size_t)b * Hn + u0 + 1] = hreg[j*2+1];
        }
    }
    load_phase_weights(dWih, dWhh, dbih, dbhh, Wout, sW, sP, tid, U0);
    __syncthreads();

    // ---------------- Decoder ----------------
    float loss_acc = 0.f;
    for (int t = 0; t < Tn; t++){
        int cur = t & 1, nxt = cur ^ 1;
        load_A(cur, B0, sA, tid);
        __syncthreads();
        mma_step<true>(sW, sA, tid, acc, accY);
        if (wn == 0 && (lane & 3) == 0){
            int g = lane >> 2;
            #pragma unroll
            for (int j = 0; j < 2; j++){
                int b = wm*16 + g + j*8;
                float yv = accY[j*2] + bo;      // y from pre-update h == y_{t-1}
                sX[b] = (t == 0) ? 0.f : yv;
                if (t > 0 && s == 0){
                    out[OFF_OUT + (size_t)(B0 + b) * Tn + (t - 1)] = yv;
                    if ((t - 1) < sSeq[b]){
                        float d = __ldg(&input[(size_t)(B0 + b) * Tn + (t - 1)]) - yv;
                        loss_acc += d * d;
                    }
                }
            }
        }
        __syncthreads();
        epilogue_frag(acc, sP, sX, 1, sSeq, hreg, tid, B0, U0, nxt, t, false);
        barN(cnt, gen, ++ph, 16u);
    }
    // final y_1023 from h_1024 (parity 0)
    load_A(0, B0, sA, tid);
    __syncthreads();
    mma_step<true>(sW, sA, tid, acc, accY);
    if (wn == 0 && (lane & 3) == 0 && s == 0){
        int g = lane >> 2;
        #pragma unroll
        for (int j = 0; j < 2; j++){
            int b = wm*16 + g + j*8;
            float yv = accY[j*2] + bo;
            out[OFF_OUT + (size_t)(B0 + b) * Tn + (Tn - 1)] = yv;
            if ((Tn - 1) < sSeq[b]){
                float d = __ldg(&input[(size_t)(B0 + b) * Tn + (Tn - 1)]) - yv;
                loss_acc += d * d;
            }
        }
    }
    __syncthreads();
    if (s == 0){
        if (wn == 0 && (lane & 3) == 0) atomicAdd(sL, loss_acc);
        __syncthreads();
        if (tid == 0){
            atomicAdd(&g_loss, sL[0]);
            atom_rel_add(&g_done, 1u);
        }
    }
    if (blockIdx.x == 0 && tid == 0){
        while (ld_acq(&g_done) < 8u) __nanosleep(128);
        float tot = g_loss;
        out[0] = tot / (float)sCnt[0];
    }
}

extern "C" void kernel_launch(void* const* d_in, const int* in_sizes, int n_in,
                              void* d_out, int out_size){
    (void)in_sizes; (void)n_in; (void)out_size;
    const float* input = (const float*)d_in[0];
    const int*   seq   = (const int*)d_in[1];
    const float* eWih  = (const float*)d_in[2];
    const float* eWhh  = (const float*)d_in[3];
    const float* ebih  = (const float*)d_in[4];
    const float* ebhh  = (const float*)d_in[5];
    const float* dWih  = (const float*)d_in[6];
    const float* dWhh  = (const float*)d_in[7];
    const float* dbih  = (const float*)d_in[8];
    const float* dbhh  = (const float*)d_in[9];
    const float* Wout  = (const float*)d_in[10];
    const float* bo    = (const float*)d_in[11];
    float* out = (float*)d_out;

    cudaFuncSetAttribute(gru_ae_kernel, cudaFuncAttributeMaxDynamicSharedMemorySize, SMEMSZ);

    cudaMemcpyAsync(out + OFF_INP, input, (size_t)Bsz * Tn * sizeof(float),
                    cudaMemcpyDeviceToDevice, 0);
    gru_ae_kernel<<<NCTA, NTHR, SMEMSZ, 0>>>(input, seq, eWih, eWhh, ebih, ebhh,
                                             dWih, dWhh, dbih, dbhh, Wout, bo, out);
}